// round 7
// baseline (speedup 1.0000x reference)
#include <cuda_runtime.h>
#include <math.h>

#define B_   16
#define L_   1534
#define C_   16
#define SZ_  512
#define O1_  1023
#define O2_  512
#define EPS_ 1e-3f

__device__ __align__(16) float g_h1t[(O1_ + 1) * B_];   // h1 transposed: [o][b]
__device__ __align__(16) float g_h2t[O2_ * B_];         // h2 transposed: [o][b]
__device__ float g_gate[B_];
__device__ unsigned g_cnt = 0;
__device__ volatile unsigned g_flag = 0;

__device__ __forceinline__ void fma2(unsigned long long& d,
                                     unsigned long long a,
                                     unsigned long long b) {
    asm("fma.rn.f32x2 %0, %1, %2, %0;" : "+l"(d) : "l"(a), "l"(b));
}
__device__ __forceinline__ float2 unpack2(unsigned long long v) {
    float2 r;
    asm("mov.b64 {%0, %1}, %2;" : "=f"(r.x), "=f"(r.y) : "l"(v));
    return r;
}

// ---------------------------------------------------------------------------
// K1: h1[o][b] = elu( sum_{s,c} x[b,o+s,c] * W1[o,s,c] + b1[o] )
// (unchanged from R6 — proven ~10.5us; also resets K2's sync state)
// ---------------------------------------------------------------------------
__global__ void __launch_bounds__(256) k_stage1(const float* __restrict__ x,
                                                const float* __restrict__ W1,
                                                const float* __restrict__ b1) {
    const int t    = threadIdx.x;
    const int lane = t & 31;
    const int warp = t >> 5;
    const int cq   = lane & 3;
    const int rp   = lane >> 2;
    const int bq   = warp & 3;
    const int kh   = warp >> 2;
    const int o0   = blockIdx.x * 8;
    const bool full = (o0 + 8 <= O1_);

    if (blockIdx.x == 0 && t == 0) { g_cnt = 0; g_flag = 0; }  // reset K2 sync

    unsigned long long acc[8][4];
#pragma unroll
    for (int o = 0; o < 8; o++)
#pragma unroll
        for (int i = 0; i < 4; i++) acc[o][i] = 0ull;

    const int k_begin = kh ? 32 : 0;

    const float* px[4];
#pragma unroll
    for (int i = 0; i < 4; i++)
        px[i] = x + ((4 * bq + i) * L_ + o0 + rp) * 16 + 4 * cq + k_begin * 128;
    const float* pw = W1 + o0 * (SZ_ * C_) + rp * 16 + 4 * cq + k_begin * 128;

    // ---- prologue (kh=0 only), k=0, d=rp: valid o <= rp ----
    if (kh == 0) {
        ulonglong2 xv[4];
#pragma unroll
        for (int i = 0; i < 4; i++) xv[i] = *(const ulonglong2*)px[i];
#pragma unroll
        for (int o = 0; o < 8; o++) {
            if (o <= rp && (full || o0 + o < O1_)) {
                ulonglong2 wv = *(const ulonglong2*)(pw + o * 8176);
#pragma unroll
                for (int i = 0; i < 4; i++) {
                    fma2(acc[o][i], wv.x, xv[i].x);
                    fma2(acc[o][i], wv.y, xv[i].y);
                }
            }
        }
#pragma unroll
        for (int i = 0; i < 4; i++) px[i] += 128;
        pw += 128;
    }

    // ---- interior, software-pipelined double buffer ----
    const int kcount = kh ? 32 : 31;

    ulonglong2 xv[2][4], wv[2][8];
#pragma unroll
    for (int i = 0; i < 4; i++) xv[0][i] = *(const ulonglong2*)px[i];
#pragma unroll
    for (int o = 0; o < 8; o++) wv[0][o] = *(const ulonglong2*)(pw + o * 8176);
#pragma unroll
    for (int i = 0; i < 4; i++) px[i] += 128;
    pw += 128;

    if (full) {
#pragma unroll 2
        for (int k = 0; k < kcount; k++) {
            const int cur = k & 1, nxt = cur ^ 1;
            if (k + 1 < kcount) {
#pragma unroll
                for (int i = 0; i < 4; i++) xv[nxt][i] = *(const ulonglong2*)px[i];
#pragma unroll
                for (int o = 0; o < 8; o++) wv[nxt][o] = *(const ulonglong2*)(pw + o * 8176);
#pragma unroll
                for (int i = 0; i < 4; i++) px[i] += 128;
                pw += 128;
            }
#pragma unroll
            for (int o = 0; o < 8; o++)
#pragma unroll
                for (int i = 0; i < 4; i++) {
                    fma2(acc[o][i], wv[cur][o].x, xv[cur][i].x);
                    fma2(acc[o][i], wv[cur][o].y, xv[cur][i].y);
                }
        }
    } else {
#pragma unroll 2
        for (int k = 0; k < kcount; k++) {
            const int cur = k & 1, nxt = cur ^ 1;
            if (k + 1 < kcount) {
#pragma unroll
                for (int i = 0; i < 4; i++) xv[nxt][i] = *(const ulonglong2*)px[i];
#pragma unroll
                for (int o = 0; o < 8; o++)
                    if (o0 + o < O1_) wv[nxt][o] = *(const ulonglong2*)(pw + o * 8176);
#pragma unroll
                for (int i = 0; i < 4; i++) px[i] += 128;
                pw += 128;
            }
#pragma unroll
            for (int o = 0; o < 8; o++) {
                if (o0 + o < O1_) {
#pragma unroll
                    for (int i = 0; i < 4; i++) {
                        fma2(acc[o][i], wv[cur][o].x, xv[cur][i].x);
                        fma2(acc[o][i], wv[cur][o].y, xv[cur][i].y);
                    }
                }
            }
        }
    }

    // ---- epilogue (kh=1 only), k=64, d=512+rp: valid o > rp ----
    if (kh == 1) {
        int row = o0 + 512 + rp;
        if (row > L_ - 1) row = L_ - 1;     // clamped slots only hit masked o's
        ulonglong2 exv[4];
#pragma unroll
        for (int i = 0; i < 4; i++)
            exv[i] = *(const ulonglong2*)(x + ((4 * bq + i) * L_ + row) * 16 + 4 * cq);
#pragma unroll
        for (int o = 0; o < 8; o++) {
            if (o > rp && (full || o0 + o < O1_)) {
                ulonglong2 ewv = *(const ulonglong2*)(pw + o * 8176);
#pragma unroll
                for (int i = 0; i < 4; i++) {
                    fma2(acc[o][i], ewv.x, exv[i].x);
                    fma2(acc[o][i], ewv.y, exv[i].y);
                }
            }
        }
    }

    // ---- reduction ----
    float s[8][4];
#pragma unroll
    for (int o = 0; o < 8; o++)
#pragma unroll
        for (int i = 0; i < 4; i++) {
            float2 p = unpack2(acc[o][i]);
            float v = p.x + p.y;
            v += __shfl_xor_sync(0xffffffffu, v, 1);
            v += __shfl_xor_sync(0xffffffffu, v, 2);
            s[o][i] = v;
        }

    __shared__ float red[64][36];
    if (cq == 0) {
        int contrib = warp * 8 + rp;
#pragma unroll
        for (int o = 0; o < 8; o++) {
            float4 v4 = make_float4(s[o][0], s[o][1], s[o][2], s[o][3]);
            *(float4*)&red[contrib][o * 4] = v4;
        }
    }
    __syncthreads();

    if (t < 128) {
        int o   = t >> 4;
        int b   = t & 15;
        int bqq = b >> 2;
        int bl  = b & 3;
        float v = 0.f;
#pragma unroll
        for (int k2 = 0; k2 < 2; k2++)
#pragma unroll
            for (int r = 0; r < 8; r++)
                v += red[(k2 * 4 + bqq) * 8 + r][o * 4 + bl];
        int og = o0 + o;
        if (og < O1_) {
            float h = v + b1[og];
            h = (h > 0.f) ? h : expm1f(h);
            g_h1t[og * 16 + b] = h;
        }
    }
}

// ---------------------------------------------------------------------------
// K2 (fused stages 2+3+4), 512 blocks x 256 threads, all co-resident
// (>=4 blocks/SM guaranteed by launch_bounds; 148*4=592 >= 512 -> no deadlock).
//
//  A) stage2: block bid computes h2[bid][0..15].
//  B) fenced atomic counter; LAST block to finish computes gate[0..15]
//     (stage3); everyone else spins on g_flag (volatile, nanosleep).
//  C) stage4: blocks 0..383, one float4 per thread (384*256 = 98304 = out/4).
// ---------------------------------------------------------------------------
__global__ void __launch_bounds__(256, 4)
k_fused234(const float* __restrict__ x,   const float* __restrict__ W2,
           const float* __restrict__ b2,  const float* __restrict__ Wl,
           const float* __restrict__ bl,  const float* __restrict__ Ws,
           const float* __restrict__ bs,  const float* __restrict__ gamma,
           const float* __restrict__ beta,const float* __restrict__ mm,
           const float* __restrict__ mv,  float* __restrict__ out) {
    const int t    = threadIdx.x;
    const int bid  = blockIdx.x;
    const int lane = t & 31;
    const int warp = t >> 5;

    __shared__ float part[8][16];
    __shared__ float sl[8][16], ss[8][16];
    __shared__ unsigned s_last;

    // ---------- stage 2: h2[bid][b] ----------
    {
        int o  = bid;
        int b  = t & 15;
        int sp = t >> 4;
        float acc = 0.f;
#pragma unroll
        for (int k = 0; k < 32; k++) {
            int s = sp + (k << 4);
            acc = fmaf(g_h1t[(o + s) * 16 + b], W2[o * SZ_ + s], acc);
        }
        acc += __shfl_down_sync(0xffffffffu, acc, 16);
        if (lane < 16) part[warp][lane] = acc;
        __syncthreads();
        if (t < 16) {
            float v = 0.f;
#pragma unroll
            for (int w = 0; w < 8; w++) v += part[w][t];
            g_h2t[o * 16 + t] = v + b2[o];
        }
    }

    // ---------- elect last block ----------
    __threadfence();                     // publish h2
    __syncthreads();
    if (t == 0) {
        unsigned v = atomicAdd(&g_cnt, 1u);
        s_last = (v == (unsigned)(gridDim.x - 1)) ? 1u : 0u;
    }
    __syncthreads();

    if (s_last) {
        // ---------- stage 3 (last block only): gate[b] ----------
        __threadfence();                 // acquire all blocks' h2
        int b = t & 15;
        int p = t >> 4;
        float al = 0.f, as_ = 0.f;
#pragma unroll
        for (int k = 0; k < 32; k++) {
            int s   = p + (k << 4);
            float h = g_h2t[s * 16 + b];
            al  = fmaf(h, Wl[s], al);
            as_ = fmaf(h, Ws[s], as_);
        }
        al  += __shfl_down_sync(0xffffffffu, al, 16);
        as_ += __shfl_down_sync(0xffffffffu, as_, 16);
        if (lane < 16) { sl[warp][lane] = al; ss[warp][lane] = as_; }
        __syncthreads();
        if (t < 16) {
            float Lv = 0.f, Sv = 0.f;
#pragma unroll
            for (int w = 0; w < 8; w++) { Lv += sl[w][t]; Sv += ss[w][t]; }
            Lv += bl[0];
            Sv += bs[0];
            g_gate[t] = Lv * (1.f / (1.f + expf(-Sv)));
        }
        __syncthreads();
        if (t == 0) { __threadfence(); g_flag = 1u; }
    } else {
        if (t == 0) {
            while (g_flag == 0u) __nanosleep(32);
        }
    }
    __syncthreads();
    __threadfence();                     // acquire gate

    // ---------- stage 4: blocks 0..383, one float4 each ----------
    if (bid < 384) {
        int i4   = bid * 256 + t;        // [0, 98304)
        int cq   = i4 & 3;
        int c0   = 4 * cq;
        int rest = i4 >> 2;
        int l    = rest % (L_ + 1);
        int b    = rest / (L_ + 1);

        float4 xv = make_float4(0.f, 0.f, 0.f, 0.f);
        if (l < L_) xv = *(const float4*)(x + (b * L_ + l) * 16 + c0);

        float g = g_gate[b];
        float sx = rsqrtf(mv[c0 + 0] + EPS_) * gamma[c0 + 0];
        float sy = rsqrtf(mv[c0 + 1] + EPS_) * gamma[c0 + 1];
        float sz = rsqrtf(mv[c0 + 2] + EPS_) * gamma[c0 + 2];
        float sw = rsqrtf(mv[c0 + 3] + EPS_) * gamma[c0 + 3];
        float4 r;
        r.x = (xv.x + g - mm[c0 + 0]) * sx + beta[c0 + 0];
        r.y = (xv.y + g - mm[c0 + 1]) * sy + beta[c0 + 1];
        r.z = (xv.z + g - mm[c0 + 2]) * sz + beta[c0 + 2];
        r.w = (xv.w + g - mm[c0 + 3]) * sw + beta[c0 + 3];
        ((float4*)out)[i4] = r;
    }
}

// ---------------------------------------------------------------------------
extern "C" void kernel_launch(void* const* d_in, const int* in_sizes, int n_in,
                              void* d_out, int out_size) {
    const float* x     = (const float*)d_in[0];
    const float* W1    = (const float*)d_in[1];
    const float* b1    = (const float*)d_in[2];
    const float* W2    = (const float*)d_in[3];
    const float* b2    = (const float*)d_in[4];
    const float* Wl    = (const float*)d_in[5];
    const float* bl    = (const float*)d_in[6];
    const float* Ws    = (const float*)d_in[7];
    const float* bs    = (const float*)d_in[8];
    const float* gamma = (const float*)d_in[9];
    const float* beta  = (const float*)d_in[10];
    const float* mm    = (const float*)d_in[11];
    const float* mv    = (const float*)d_in[12];
    float* out = (float*)d_out;

    k_stage1<<<(O1_ + 7) / 8, 256>>>(x, W1, b1);
    k_fused234<<<O2_, 256>>>(x, W2, b2, Wl, bl, Ws, bs,
                             gamma, beta, mm, mv, out);
}

// round 8
// speedup vs baseline: 1.0158x; 1.0158x over previous
#include <cuda_runtime.h>
#include <math.h>

#define B_   16
#define L_   1534
#define C_   16
#define SZ_  512
#define O1_  1023
#define O2_  512
#define EPS_ 1e-3f
#define GATE_BLKS 128          // 16 batches x 8 o-chunks
#define OUT_BLKS  384          // 384*256 float4 = full output

__device__ __align__(16) float g_h1t[(O1_ + 1) * B_];   // h1 transposed: [o][b]
__device__ float g_pAL[16][8];   // gate partials: [batch][o-chunk]
__device__ float g_pAS[16][8];
__device__ unsigned g_cnt = 0;

__device__ __forceinline__ void fma2(unsigned long long& d,
                                     unsigned long long a,
                                     unsigned long long b) {
    asm("fma.rn.f32x2 %0, %1, %2, %0;" : "+l"(d) : "l"(a), "l"(b));
}
__device__ __forceinline__ float2 unpack2(unsigned long long v) {
    float2 r;
    asm("mov.b64 {%0, %1}, %2;" : "=f"(r.x), "=f"(r.y) : "l"(v));
    return r;
}

// ---------------------------------------------------------------------------
// K1: h1[o][b] = elu( sum_{s,c} x[b,o+s,c] * W1[o,s,c] + b1[o] )
// (proven R6 version; also resets K2's sync counter)
// ---------------------------------------------------------------------------
__global__ void __launch_bounds__(256) k_stage1(const float* __restrict__ x,
                                                const float* __restrict__ W1,
                                                const float* __restrict__ b1) {
    const int t    = threadIdx.x;
    const int lane = t & 31;
    const int warp = t >> 5;
    const int cq   = lane & 3;
    const int rp   = lane >> 2;
    const int bq   = warp & 3;
    const int kh   = warp >> 2;
    const int o0   = blockIdx.x * 8;
    const bool full = (o0 + 8 <= O1_);

    if (blockIdx.x == 0 && t == 0) g_cnt = 0;   // reset K2 sync (kernel-boundary ordered)

    unsigned long long acc[8][4];
#pragma unroll
    for (int o = 0; o < 8; o++)
#pragma unroll
        for (int i = 0; i < 4; i++) acc[o][i] = 0ull;

    const int k_begin = kh ? 32 : 0;

    const float* px[4];
#pragma unroll
    for (int i = 0; i < 4; i++)
        px[i] = x + ((4 * bq + i) * L_ + o0 + rp) * 16 + 4 * cq + k_begin * 128;
    const float* pw = W1 + o0 * (SZ_ * C_) + rp * 16 + 4 * cq + k_begin * 128;

    // ---- prologue (kh=0 only), k=0, d=rp: valid o <= rp ----
    if (kh == 0) {
        ulonglong2 xv[4];
#pragma unroll
        for (int i = 0; i < 4; i++) xv[i] = *(const ulonglong2*)px[i];
#pragma unroll
        for (int o = 0; o < 8; o++) {
            if (o <= rp && (full || o0 + o < O1_)) {
                ulonglong2 wv = *(const ulonglong2*)(pw + o * 8176);
#pragma unroll
                for (int i = 0; i < 4; i++) {
                    fma2(acc[o][i], wv.x, xv[i].x);
                    fma2(acc[o][i], wv.y, xv[i].y);
                }
            }
        }
#pragma unroll
        for (int i = 0; i < 4; i++) px[i] += 128;
        pw += 128;
    }

    // ---- interior, software-pipelined double buffer ----
    const int kcount = kh ? 32 : 31;

    ulonglong2 xv[2][4], wv[2][8];
#pragma unroll
    for (int i = 0; i < 4; i++) xv[0][i] = *(const ulonglong2*)px[i];
#pragma unroll
    for (int o = 0; o < 8; o++) wv[0][o] = *(const ulonglong2*)(pw + o * 8176);
#pragma unroll
    for (int i = 0; i < 4; i++) px[i] += 128;
    pw += 128;

    if (full) {
#pragma unroll 2
        for (int k = 0; k < kcount; k++) {
            const int cur = k & 1, nxt = cur ^ 1;
            if (k + 1 < kcount) {
#pragma unroll
                for (int i = 0; i < 4; i++) xv[nxt][i] = *(const ulonglong2*)px[i];
#pragma unroll
                for (int o = 0; o < 8; o++) wv[nxt][o] = *(const ulonglong2*)(pw + o * 8176);
#pragma unroll
                for (int i = 0; i < 4; i++) px[i] += 128;
                pw += 128;
            }
#pragma unroll
            for (int o = 0; o < 8; o++)
#pragma unroll
                for (int i = 0; i < 4; i++) {
                    fma2(acc[o][i], wv[cur][o].x, xv[cur][i].x);
                    fma2(acc[o][i], wv[cur][o].y, xv[cur][i].y);
                }
        }
    } else {
#pragma unroll 2
        for (int k = 0; k < kcount; k++) {
            const int cur = k & 1, nxt = cur ^ 1;
            if (k + 1 < kcount) {
#pragma unroll
                for (int i = 0; i < 4; i++) xv[nxt][i] = *(const ulonglong2*)px[i];
#pragma unroll
                for (int o = 0; o < 8; o++)
                    if (o0 + o < O1_) wv[nxt][o] = *(const ulonglong2*)(pw + o * 8176);
#pragma unroll
                for (int i = 0; i < 4; i++) px[i] += 128;
                pw += 128;
            }
#pragma unroll
            for (int o = 0; o < 8; o++) {
                if (o0 + o < O1_) {
#pragma unroll
                    for (int i = 0; i < 4; i++) {
                        fma2(acc[o][i], wv[cur][o].x, xv[cur][i].x);
                        fma2(acc[o][i], wv[cur][o].y, xv[cur][i].y);
                    }
                }
            }
        }
    }

    // ---- epilogue (kh=1 only), k=64, d=512+rp: valid o > rp ----
    if (kh == 1) {
        int row = o0 + 512 + rp;
        if (row > L_ - 1) row = L_ - 1;     // clamped slots only hit masked o's
        ulonglong2 exv[4];
#pragma unroll
        for (int i = 0; i < 4; i++)
            exv[i] = *(const ulonglong2*)(x + ((4 * bq + i) * L_ + row) * 16 + 4 * cq);
#pragma unroll
        for (int o = 0; o < 8; o++) {
            if (o > rp && (full || o0 + o < O1_)) {
                ulonglong2 ewv = *(const ulonglong2*)(pw + o * 8176);
#pragma unroll
                for (int i = 0; i < 4; i++) {
                    fma2(acc[o][i], ewv.x, exv[i].x);
                    fma2(acc[o][i], ewv.y, exv[i].y);
                }
            }
        }
    }

    // ---- reduction ----
    float s[8][4];
#pragma unroll
    for (int o = 0; o < 8; o++)
#pragma unroll
        for (int i = 0; i < 4; i++) {
            float2 p = unpack2(acc[o][i]);
            float v = p.x + p.y;
            v += __shfl_xor_sync(0xffffffffu, v, 1);
            v += __shfl_xor_sync(0xffffffffu, v, 2);
            s[o][i] = v;
        }

    __shared__ float red[64][36];
    if (cq == 0) {
        int contrib = warp * 8 + rp;
#pragma unroll
        for (int o = 0; o < 8; o++) {
            float4 v4 = make_float4(s[o][0], s[o][1], s[o][2], s[o][3]);
            *(float4*)&red[contrib][o * 4] = v4;
        }
    }
    __syncthreads();

    if (t < 128) {
        int o   = t >> 4;
        int b   = t & 15;
        int bqq = b >> 2;
        int bl  = b & 3;
        float v = 0.f;
#pragma unroll
        for (int k2 = 0; k2 < 2; k2++)
#pragma unroll
            for (int r = 0; r < 8; r++)
                v += red[(k2 * 4 + bqq) * 8 + r][o * 4 + bl];
        int og = o0 + o;
        if (og < O1_) {
            float h = v + b1[og];
            h = (h > 0.f) ? h : expm1f(h);
            g_h1t[og * 16 + b] = h;
        }
    }
}

// ---------------------------------------------------------------------------
// K2: fused gate + output. 512 blocks x 256 threads, all co-resident
// (occ >= 4 by launch_bounds; 148*4 = 592 >= 512 -> spin is deadlock-free).
//
//  Blocks 0..127 (b = bid>>3, chunk = bid&7): partial gate dots over
//    o in [chunk*64, chunk*64+64):
//      h2(o,b) = b2[o] + sum_s W2[o,s]*h1[o+s][b]
//      pAL += Wl[o]*h2(o,b);  pAS += Ws[o]*h2(o,b)
//    h1 column window staged in smem; W2 rows read as coalesced float4
//    (W2 read exactly once chip-wide). Partials to per-slot globals
//    (deterministic), then ONE counter atomicAdd (128 arrivals total).
//
//  Blocks 128..511: spin until counter==128, rebuild gate[b] from the 8
//    partials in fixed order, then one float4 of output per thread.
// ---------------------------------------------------------------------------
__global__ void __launch_bounds__(256, 4)
k_gate_out(const float* __restrict__ x,   const float* __restrict__ W2,
           const float* __restrict__ b2,  const float* __restrict__ Wl,
           const float* __restrict__ bl,  const float* __restrict__ Ws,
           const float* __restrict__ bs,  const float* __restrict__ gamma,
           const float* __restrict__ beta,const float* __restrict__ mm,
           const float* __restrict__ mv,  float* __restrict__ out) {
    const int t    = threadIdx.x;
    const int bid  = blockIdx.x;
    const int lane = t & 31;
    const int warp = t >> 5;

    if (bid < GATE_BLKS) {
        // ---------------- gate-partial producer ----------------
        const int b  = bid >> 3;
        const int ch = bid & 7;
        const int o0 = ch * 64;

        __shared__ float s_h1[576];
        __shared__ float s_al[8], s_as[8];

        for (int j = t; j < 576; j += 256)
            s_h1[j] = g_h1t[(o0 + j) * 16 + b];
        __syncthreads();

        // warp handles 8 o's: o_loc = warp*8 + i
        float al = 0.f, as_ = 0.f;
#pragma unroll
        for (int i = 0; i < 8; i++) {
            int ol = warp * 8 + i;
            int o  = o0 + ol;
            const float4* wrow = (const float4*)(W2 + o * SZ_);
            float acc = 0.f;
#pragma unroll
            for (int it = 0; it < 4; it++) {
                int s4 = it * 32 + lane;          // float4 index; s = s4*4
                float4 wv = wrow[s4];
                int s  = s4 * 4;
                acc += wv.x * s_h1[ol + s]     + wv.y * s_h1[ol + s + 1]
                     + wv.z * s_h1[ol + s + 2] + wv.w * s_h1[ol + s + 3];
            }
#pragma unroll
            for (int off = 16; off; off >>= 1)
                acc += __shfl_down_sync(0xffffffffu, acc, off);
            if (lane == 0) {
                float h2v = acc + b2[o];
                al  = fmaf(Wl[o], h2v, al);
                as_ = fmaf(Ws[o], h2v, as_);
            }
        }
        if (lane == 0) { s_al[warp] = al; s_as[warp] = as_; }
        __syncthreads();

        if (t == 0) {
            float AL = 0.f, AS = 0.f;
#pragma unroll
            for (int w = 0; w < 8; w++) { AL += s_al[w]; AS += s_as[w]; }
            g_pAL[b][ch] = AL;
            g_pAS[b][ch] = AS;
            __threadfence();
            atomicAdd(&g_cnt, 1u);
        }
    } else {
        // ---------------- output consumer ----------------
        if (t == 0) {
            while (*(volatile unsigned*)&g_cnt < (unsigned)GATE_BLKS)
                __nanosleep(64);
        }
        __syncthreads();
        __threadfence();    // acquire partials

        int i4   = (bid - GATE_BLKS) * 256 + t;   // [0, 98304)
        int cq   = i4 & 3;
        int c0   = 4 * cq;
        int rest = i4 >> 2;
        int l    = rest % (L_ + 1);
        int b    = rest / (L_ + 1);

        float AL = bl[0], AS = bs[0];
#pragma unroll
        for (int chh = 0; chh < 8; chh++) { AL += g_pAL[b][chh]; AS += g_pAS[b][chh]; }
        float g = AL * (1.f / (1.f + expf(-AS)));

        float4 xv = make_float4(0.f, 0.f, 0.f, 0.f);
        if (l < L_) xv = *(const float4*)(x + (b * L_ + l) * 16 + c0);

        float sx = rsqrtf(mv[c0 + 0] + EPS_) * gamma[c0 + 0];
        float sy = rsqrtf(mv[c0 + 1] + EPS_) * gamma[c0 + 1];
        float sz = rsqrtf(mv[c0 + 2] + EPS_) * gamma[c0 + 2];
        float sw = rsqrtf(mv[c0 + 3] + EPS_) * gamma[c0 + 3];
        float4 r;
        r.x = (xv.x + g - mm[c0 + 0]) * sx + beta[c0 + 0];
        r.y = (xv.y + g - mm[c0 + 1]) * sy + beta[c0 + 1];
        r.z = (xv.z + g - mm[c0 + 2]) * sz + beta[c0 + 2];
        r.w = (xv.w + g - mm[c0 + 3]) * sw + beta[c0 + 3];
        ((float4*)out)[i4] = r;
    }
}

// ---------------------------------------------------------------------------
extern "C" void kernel_launch(void* const* d_in, const int* in_sizes, int n_in,
                              void* d_out, int out_size) {
    const float* x     = (const float*)d_in[0];
    const float* W1    = (const float*)d_in[1];
    const float* b1    = (const float*)d_in[2];
    const float* W2    = (const float*)d_in[3];
    const float* b2    = (const float*)d_in[4];
    const float* Wl    = (const float*)d_in[5];
    const float* bl    = (const float*)d_in[6];
    const float* Ws    = (const float*)d_in[7];
    const float* bs    = (const float*)d_in[8];
    const float* gamma = (const float*)d_in[9];
    const float* beta  = (const float*)d_in[10];
    const float* mm    = (const float*)d_in[11];
    const float* mv    = (const float*)d_in[12];
    float* out = (float*)d_out;

    k_stage1<<<(O1_ + 7) / 8, 256>>>(x, W1, b1);
    k_gate_out<<<GATE_BLKS + OUT_BLKS, 256>>>(x, W2, b2, Wl, bl, Ws, bs,
                                              gamma, beta, mm, mv, out);
}

// round 9
// speedup vs baseline: 1.5923x; 1.5675x over previous
#include <cuda_runtime.h>
#include <math.h>

#define B_   16
#define L_   1534
#define C_   16
#define SZ_  512
#define O1_  1023
#define O2_  512
#define EPS_ 1e-3f

__device__ __align__(16) float g_h1t[(O1_ + 1) * B_];   // h1 transposed: [o][b]
__device__ __align__(16) float g_uL[1024];   // uL[j] = sum_o Wl[o]*W2[o][j-o]
__device__ __align__(16) float g_uS[1024];
__device__ float g_const[2];                 // constL, constS

__device__ __forceinline__ void fma2(unsigned long long& d,
                                     unsigned long long a,
                                     unsigned long long b) {
    asm("fma.rn.f32x2 %0, %1, %2, %0;" : "+l"(d) : "l"(a), "l"(b));
}
__device__ __forceinline__ float2 unpack2(unsigned long long v) {
    float2 r;
    asm("mov.b64 {%0, %1}, %2;" : "=f"(r.x), "=f"(r.y) : "l"(v));
    return r;
}

// ---------------------------------------------------------------------------
// K1: 144 blocks.
//   bid 0..127 : stage1 (proven R6 code, unchanged):
//       h1[o][b] = elu( sum_{s,c} x[b,o+s,c]*W1[o,s,c] + b1[o] )
//   bid 128..143: gate-weight precompute (independent of stage1, hidden
//       under it): for 64 j's, uL[j] = sum_o Wl[o]*W2[o][j-o], uS likewise.
//       Block 128 also computes constL = bl + sum_o Wl[o]*b2[o], constS.
// ---------------------------------------------------------------------------
__global__ void __launch_bounds__(256) k_stage1_prep(
        const float* __restrict__ x,  const float* __restrict__ W1,
        const float* __restrict__ b1, const float* __restrict__ W2,
        const float* __restrict__ b2, const float* __restrict__ Wl,
        const float* __restrict__ bl, const float* __restrict__ Ws,
        const float* __restrict__ bs) {
    const int t    = threadIdx.x;
    const int bid  = blockIdx.x;
    const int lane = t & 31;
    const int warp = t >> 5;

    if (bid >= 128) {
        // ================= PREP: u vectors =================
        const int ch = bid - 128;        // 0..15
        const int j0 = ch * 64;
        const int jl = t & 63;           // j offset within chunk
        const int op = t >> 6;           // o phase 0..3
        const int j  = j0 + jl;

        float aL = 0.f, aS = 0.f;
        // o = op, op+4, ...; s = j - o must be in [0, 512)
        for (int o = op; o < SZ_; o += 4) {
            int s = j - o;
            if (0 <= s && s < SZ_) {
                float w = W2[o * SZ_ + s];
                aL = fmaf(Wl[o], w, aL);
                aS = fmaf(Ws[o], w, aS);
            }
        }
        __shared__ float sL[4][64], sS[4][64];
        sL[op][jl] = aL;
        sS[op][jl] = aS;
        __syncthreads();
        if (t < 64) {
            float vL = sL[0][t] + sL[1][t] + sL[2][t] + sL[3][t];
            float vS = sS[0][t] + sS[1][t] + sS[2][t] + sS[3][t];
            g_uL[j0 + t] = vL;
            g_uS[j0 + t] = vS;
        }
        // constants (block 128, warp 3 — keeps warp 0/1 load pattern clean)
        if (ch == 0 && warp == 3) {
            float cL = 0.f, cS = 0.f;
            for (int o = lane; o < SZ_; o += 32) {
                float bv = b2[o];
                cL = fmaf(Wl[o], bv, cL);
                cS = fmaf(Ws[o], bv, cS);
            }
#pragma unroll
            for (int off = 16; off; off >>= 1) {
                cL += __shfl_down_sync(0xffffffffu, cL, off);
                cS += __shfl_down_sync(0xffffffffu, cS, off);
            }
            if (lane == 0) {
                g_const[0] = bl[0] + cL;
                g_const[1] = bs[0] + cS;
            }
        }
        return;
    }

    // ================= STAGE 1 (unchanged R6) =================
    const int cq   = lane & 3;
    const int rp   = lane >> 2;
    const int bq   = warp & 3;
    const int kh   = warp >> 2;
    const int o0   = bid * 8;
    const bool full = (o0 + 8 <= O1_);

    unsigned long long acc[8][4];
#pragma unroll
    for (int o = 0; o < 8; o++)
#pragma unroll
        for (int i = 0; i < 4; i++) acc[o][i] = 0ull;

    const int k_begin = kh ? 32 : 0;

    const float* px[4];
#pragma unroll
    for (int i = 0; i < 4; i++)
        px[i] = x + ((4 * bq + i) * L_ + o0 + rp) * 16 + 4 * cq + k_begin * 128;
    const float* pw = W1 + o0 * (SZ_ * C_) + rp * 16 + 4 * cq + k_begin * 128;

    // ---- prologue (kh=0 only), k=0, d=rp: valid o <= rp ----
    if (kh == 0) {
        ulonglong2 xv[4];
#pragma unroll
        for (int i = 0; i < 4; i++) xv[i] = *(const ulonglong2*)px[i];
#pragma unroll
        for (int o = 0; o < 8; o++) {
            if (o <= rp && (full || o0 + o < O1_)) {
                ulonglong2 wv = *(const ulonglong2*)(pw + o * 8176);
#pragma unroll
                for (int i = 0; i < 4; i++) {
                    fma2(acc[o][i], wv.x, xv[i].x);
                    fma2(acc[o][i], wv.y, xv[i].y);
                }
            }
        }
#pragma unroll
        for (int i = 0; i < 4; i++) px[i] += 128;
        pw += 128;
    }

    // ---- interior, software-pipelined double buffer ----
    const int kcount = kh ? 32 : 31;

    ulonglong2 xv[2][4], wv[2][8];
#pragma unroll
    for (int i = 0; i < 4; i++) xv[0][i] = *(const ulonglong2*)px[i];
#pragma unroll
    for (int o = 0; o < 8; o++) wv[0][o] = *(const ulonglong2*)(pw + o * 8176);
#pragma unroll
    for (int i = 0; i < 4; i++) px[i] += 128;
    pw += 128;

    if (full) {
#pragma unroll 2
        for (int k = 0; k < kcount; k++) {
            const int cur = k & 1, nxt = cur ^ 1;
            if (k + 1 < kcount) {
#pragma unroll
                for (int i = 0; i < 4; i++) xv[nxt][i] = *(const ulonglong2*)px[i];
#pragma unroll
                for (int o = 0; o < 8; o++) wv[nxt][o] = *(const ulonglong2*)(pw + o * 8176);
#pragma unroll
                for (int i = 0; i < 4; i++) px[i] += 128;
                pw += 128;
            }
#pragma unroll
            for (int o = 0; o < 8; o++)
#pragma unroll
                for (int i = 0; i < 4; i++) {
                    fma2(acc[o][i], wv[cur][o].x, xv[cur][i].x);
                    fma2(acc[o][i], wv[cur][o].y, xv[cur][i].y);
                }
        }
    } else {
#pragma unroll 2
        for (int k = 0; k < kcount; k++) {
            const int cur = k & 1, nxt = cur ^ 1;
            if (k + 1 < kcount) {
#pragma unroll
                for (int i = 0; i < 4; i++) xv[nxt][i] = *(const ulonglong2*)px[i];
#pragma unroll
                for (int o = 0; o < 8; o++)
                    if (o0 + o < O1_) wv[nxt][o] = *(const ulonglong2*)(pw + o * 8176);
#pragma unroll
                for (int i = 0; i < 4; i++) px[i] += 128;
                pw += 128;
            }
#pragma unroll
            for (int o = 0; o < 8; o++) {
                if (o0 + o < O1_) {
#pragma unroll
                    for (int i = 0; i < 4; i++) {
                        fma2(acc[o][i], wv[cur][o].x, xv[cur][i].x);
                        fma2(acc[o][i], wv[cur][o].y, xv[cur][i].y);
                    }
                }
            }
        }
    }

    // ---- epilogue (kh=1 only), k=64, d=512+rp: valid o > rp ----
    if (kh == 1) {
        int row = o0 + 512 + rp;
        if (row > L_ - 1) row = L_ - 1;     // clamped slots only hit masked o's
        ulonglong2 exv[4];
#pragma unroll
        for (int i = 0; i < 4; i++)
            exv[i] = *(const ulonglong2*)(x + ((4 * bq + i) * L_ + row) * 16 + 4 * cq);
#pragma unroll
        for (int o = 0; o < 8; o++) {
            if (o > rp && (full || o0 + o < O1_)) {
                ulonglong2 ewv = *(const ulonglong2*)(pw + o * 8176);
#pragma unroll
                for (int i = 0; i < 4; i++) {
                    fma2(acc[o][i], ewv.x, exv[i].x);
                    fma2(acc[o][i], ewv.y, exv[i].y);
                }
            }
        }
    }

    // ---- reduction ----
    float s[8][4];
#pragma unroll
    for (int o = 0; o < 8; o++)
#pragma unroll
        for (int i = 0; i < 4; i++) {
            float2 p = unpack2(acc[o][i]);
            float v = p.x + p.y;
            v += __shfl_xor_sync(0xffffffffu, v, 1);
            v += __shfl_xor_sync(0xffffffffu, v, 2);
            s[o][i] = v;
        }

    __shared__ float red[64][36];
    if (cq == 0) {
        int contrib = warp * 8 + rp;
#pragma unroll
        for (int o = 0; o < 8; o++) {
            float4 v4 = make_float4(s[o][0], s[o][1], s[o][2], s[o][3]);
            *(float4*)&red[contrib][o * 4] = v4;
        }
    }
    __syncthreads();

    if (t < 128) {
        int o   = t >> 4;
        int b   = t & 15;
        int bqq = b >> 2;
        int bl_ = b & 3;
        float v = 0.f;
#pragma unroll
        for (int k2 = 0; k2 < 2; k2++)
#pragma unroll
            for (int r = 0; r < 8; r++)
                v += red[(k2 * 4 + bqq) * 8 + r][o * 4 + bl_];
        int og = o0 + o;
        if (og < O1_) {
            float h = v + b1[og];
            h = (h > 0.f) ? h : expm1f(h);
            g_h1t[og * 16 + b] = h;
        }
    }
}

// ---------------------------------------------------------------------------
// K2: 384 blocks x 256 threads. Each block spans <= 2 batches of output.
// It computes the gates for those 2 batches directly (redundantly, no sync):
//   AL[b] = constL + sum_j h1[j][b]*uL[j];  AS likewise;
//   gate  = AL * sigmoid(AS)
// then writes one float4 of output per thread.
// ---------------------------------------------------------------------------
__global__ void __launch_bounds__(256) k_out(
        const float* __restrict__ x,    const float* __restrict__ gamma,
        const float* __restrict__ beta, const float* __restrict__ mm,
        const float* __restrict__ mv,   float* __restrict__ out) {
    const int t    = threadIdx.x;
    const int bid  = blockIdx.x;
    const int lane = t & 31;
    const int warp = t >> 5;

    // batches this block touches: rest in [bid*64, bid*64+64)
    const int b0 = (bid * 64) / (L_ + 1);
    const int b1i = (b0 + 1 < B_) ? b0 + 1 : b0;

    // ---- gate dot: thread handles j = t, t+256, t+512, t+768 ----
    float aL0 = 0.f, aS0 = 0.f, aL1 = 0.f, aS1 = 0.f;
#pragma unroll
    for (int it = 0; it < 4; it++) {
        int j = t + it * 256;
        if (j < O1_) {
            float ul = g_uL[j];
            float us = g_uS[j];
            float h0 = g_h1t[j * 16 + b0];
            float h1v = g_h1t[j * 16 + b1i];
            aL0 = fmaf(h0, ul, aL0);
            aS0 = fmaf(h0, us, aS0);
            aL1 = fmaf(h1v, ul, aL1);
            aS1 = fmaf(h1v, us, aS1);
        }
    }
#pragma unroll
    for (int off = 16; off; off >>= 1) {
        aL0 += __shfl_down_sync(0xffffffffu, aL0, off);
        aS0 += __shfl_down_sync(0xffffffffu, aS0, off);
        aL1 += __shfl_down_sync(0xffffffffu, aL1, off);
        aS1 += __shfl_down_sync(0xffffffffu, aS1, off);
    }
    __shared__ float rr[8][4];
    __shared__ float s_gate[2];
    if (lane == 0) {
        rr[warp][0] = aL0; rr[warp][1] = aS0;
        rr[warp][2] = aL1; rr[warp][3] = aS1;
    }
    __syncthreads();
    if (t == 0) {
        float AL0 = g_const[0], AS0 = g_const[1];
        float AL1 = g_const[0], AS1 = g_const[1];
#pragma unroll
        for (int w = 0; w < 8; w++) {
            AL0 += rr[w][0]; AS0 += rr[w][1];
            AL1 += rr[w][2]; AS1 += rr[w][3];
        }
        s_gate[0] = AL0 * (1.f / (1.f + expf(-AS0)));
        s_gate[1] = AL1 * (1.f / (1.f + expf(-AS1)));
    }
    __syncthreads();

    // ---- output: one float4 per thread ----
    int i4   = bid * 256 + t;            // [0, 98304)
    int cq   = i4 & 3;
    int c0   = 4 * cq;
    int rest = i4 >> 2;
    int l    = rest % (L_ + 1);
    int b    = rest / (L_ + 1);

    float4 xv = make_float4(0.f, 0.f, 0.f, 0.f);
    if (l < L_) xv = *(const float4*)(x + (b * L_ + l) * 16 + c0);

    float g = s_gate[b - b0];
    float sx = rsqrtf(mv[c0 + 0] + EPS_) * gamma[c0 + 0];
    float sy = rsqrtf(mv[c0 + 1] + EPS_) * gamma[c0 + 1];
    float sz = rsqrtf(mv[c0 + 2] + EPS_) * gamma[c0 + 2];
    float sw = rsqrtf(mv[c0 + 3] + EPS_) * gamma[c0 + 3];
    float4 r;
    r.x = (xv.x + g - mm[c0 + 0]) * sx + beta[c0 + 0];
    r.y = (xv.y + g - mm[c0 + 1]) * sy + beta[c0 + 1];
    r.z = (xv.z + g - mm[c0 + 2]) * sz + beta[c0 + 2];
    r.w = (xv.w + g - mm[c0 + 3]) * sw + beta[c0 + 3];
    ((float4*)out)[i4] = r;
}

// ---------------------------------------------------------------------------
extern "C" void kernel_launch(void* const* d_in, const int* in_sizes, int n_in,
                              void* d_out, int out_size) {
    const float* x     = (const float*)d_in[0];
    const float* W1    = (const float*)d_in[1];
    const float* b1    = (const float*)d_in[2];
    const float* W2    = (const float*)d_in[3];
    const float* b2    = (const float*)d_in[4];
    const float* Wl    = (const float*)d_in[5];
    const float* bl    = (const float*)d_in[6];
    const float* Ws    = (const float*)d_in[7];
    const float* bs    = (const float*)d_in[8];
    const float* gamma = (const float*)d_in[9];
    const float* beta  = (const float*)d_in[10];
    const float* mm    = (const float*)d_in[11];
    const float* mv    = (const float*)d_in[12];
    float* out = (float*)d_out;

    k_stage1_prep<<<144, 256>>>(x, W1, b1, W2, b2, Wl, bl, Ws, bs);
    k_out<<<384, 256>>>(x, gamma, beta, mm, mv, out);
}